// round 1
// baseline (speedup 1.0000x reference)
#include <cuda_runtime.h>

#define NN 64
#define CI 256
#define CO 256
#define CR 32
#define TT 64
#define VV 25
#define TV 1600   // T*V
#define UV 625    // V*V

// ---------------- scratch (device globals; no runtime allocation) ----------------
__device__ float g_xm[NN*CI*VV];     // (n, ci, v)  mean over T
__device__ float g_x1[NN*CR*VV];     // (n, r, v)
__device__ float g_x2[NN*CR*VV];
__device__ float g_aff[NN*CR*UV];    // (n, r, u*25+v)
__device__ float g_attn[NN*CO*UV];   // (n, co, u*25+v)

// ---------------- K0: xm = mean_t x ----------------
// grid (cc=64, n=64), 256 threads, chunk of 4 channels staged in smem (coalesced)
__global__ void k_xm(const float* __restrict__ x) {
    __shared__ float sx[4*TV];
    int n = blockIdx.y, cc = blockIdx.x;
    const float* xb = x + ((size_t)(n*CI + cc*4))*TV;
    for (int i = threadIdx.x; i < 4*TV; i += 256) sx[i] = xb[i];
    __syncthreads();
    if (threadIdx.x < 100) {
        int c = threadIdx.x / VV, v = threadIdx.x - c*VV;
        float s = 0.f;
        #pragma unroll
        for (int t = 0; t < TT; t++) s += sx[c*TV + t*VV + v];
        g_xm[n*(CI*VV) + cc*100 + threadIdx.x] = s * (1.0f/64.0f);
    }
}

// ---------------- K1: x1 = w1@xm + b1 ; x2 = w2@xm + b2 ----------------
__global__ void k_x12(const float* __restrict__ w1, const float* __restrict__ b1,
                      const float* __restrict__ w2, const float* __restrict__ b2) {
    __shared__ float xm_s[CI*VV];
    int n = blockIdx.x;
    for (int i = threadIdx.x; i < CI*VV; i += 256) xm_s[i] = g_xm[n*(CI*VV) + i];
    __syncthreads();
    for (int i = threadIdx.x; i < 2*CR*VV; i += 256) {
        int sel = i / (CR*VV);
        int rv  = i - sel*(CR*VV);
        int r = rv / VV, v = rv - r*VV;
        const float* w = sel ? w2 : w1;
        float s = sel ? b2[r] : b1[r];
        #pragma unroll 8
        for (int c = 0; c < CI; c++) s += w[r*CI + c] * xm_s[c*VV + v];
        (sel ? g_x2 : g_x1)[n*(CR*VV) + rv] = s;
    }
}

// ---------------- K2: aff = tanh(x1[u] - x2[v]) ----------------
__global__ void k_aff() {
    __shared__ float s1[CR*VV], s2[CR*VV];
    int n = blockIdx.x;
    for (int i = threadIdx.x; i < CR*VV; i += 256) {
        s1[i] = g_x1[n*(CR*VV) + i];
        s2[i] = g_x2[n*(CR*VV) + i];
    }
    __syncthreads();
    for (int i = threadIdx.x; i < CR*UV; i += 256) {
        int r = i / UV, uv = i - r*UV;
        int u = uv / VV, v = uv - u*VV;
        g_aff[n*(CR*UV) + i] = tanhf(s1[r*VV + u] - s2[r*VV + v]);
    }
}

// ---------------- K3: attn = w4@aff + b4 + A   (alpha == 1) ----------------
// grid (uvt=10, cot=4, n=64), 256 threads, 64x64 tile, K=32
__global__ void k_attn(const float* __restrict__ w4, const float* __restrict__ b4,
                       const float* __restrict__ A) {
    __shared__ __align__(16) float w4s[64*CR];   // [co_local][k]
    __shared__ __align__(16) float affs[CR*64];  // [k][uv_local]
    int n = blockIdx.z, cot = blockIdx.y, uvt = blockIdx.x;
    int co0 = cot*64, uv0 = uvt*64;
    int tx = threadIdx.x & 15, ty = threadIdx.x >> 4;

    for (int i = threadIdx.x; i < 64*CR; i += 256) w4s[i] = w4[co0*CR + i];
    for (int i = threadIdx.x; i < CR*64; i += 256) {
        int r = i >> 6, c = i & 63;
        affs[i] = (uv0 + c < UV) ? g_aff[n*(CR*UV) + r*UV + uv0 + c] : 0.f;
    }
    __syncthreads();

    float acc[4][4] = {};
    #pragma unroll
    for (int k = 0; k < CR; k++) {
        float4 b = *(const float4*)&affs[k*64 + tx*4];
        #pragma unroll
        for (int i = 0; i < 4; i++) {
            float a = w4s[(ty*4 + i)*CR + k];
            acc[i][0] += a*b.x; acc[i][1] += a*b.y;
            acc[i][2] += a*b.z; acc[i][3] += a*b.w;
        }
    }
    #pragma unroll
    for (int i = 0; i < 4; i++) {
        int co = co0 + ty*4 + i;
        float bb = b4[co];
        #pragma unroll
        for (int j = 0; j < 4; j++) {
            int uv = uv0 + tx*4 + j;
            if (uv < UV)
                g_attn[((size_t)n*CO + co)*UV + uv] = acc[i][j] + bb + A[uv];
        }
    }
}

// ---------------- K4: fused  x3 = w3@x + b3 ; out = contraction with attn ----------------
// grid (32 = 8 co-tiles x 4 t-tiles, n=64), 256 threads.
// CTA tile: 32 co x 16 t x (all 25 u), K=256 in 16 chunks with register prefetch.
// thread (tx,ty): co pair (2*tx, 2*tx+1), t = ty. acc0/acc1[25].
#define ATTN_STRIDE 700   // 25 u-rows padded to 28 floats
#define X3_CO_STRIDE 433  // 16 t-rows padded to 27, +1 to break bank pattern
// smem (floats): attn_s [0,22400) ; xs [22400, +7168) ; ws [+544) ; x3s reuses xs region (13856)
#define SMEM_FLOATS (22400 + 13856)

__global__ __launch_bounds__(256) void k_main(
    const float* __restrict__ x, const float* __restrict__ w3,
    const float* __restrict__ b3, float* __restrict__ out)
{
    extern __shared__ __align__(16) float sm[];
    float* attn_s = sm;
    float* xs  = sm + 22400;          // [kk][t*28+u], 16*448
    float* ws  = sm + 22400 + 7168;   // [kk][co_local], 16*34 padded
    float* x3s = sm + 22400;          // reused after mainloop

    int n  = blockIdx.y;
    int cot = blockIdx.x >> 2, tt = blockIdx.x & 3;
    int co0 = cot*32, t0 = tt*16;
    int tid = threadIdx.x;
    int tx = tid & 15, ty = tid >> 4;
    int kkL = tid >> 4, tL = tid & 15;   // staging roles: 16 kk x 16 t

    // ---- load attn tile into padded smem rows ----
    {
        const float* ab = g_attn + ((size_t)n*CO + co0)*UV;
        for (int i = tid; i < 32*ATTN_STRIDE; i += 256) {
            int co = i / ATTN_STRIDE;
            int rem = i - co*ATTN_STRIDE;
            int u = rem / 28, v = rem - u*28;
            attn_s[i] = (v < VV) ? ab[co*UV + u*VV + v] : 0.f;
        }
    }

    float acc0[25], acc1[25];
    #pragma unroll
    for (int u = 0; u < 25; u++) { acc0[u] = 0.f; acc1[u] = 0.f; }

    const float* xbase = x + ((size_t)n*CI)*TV + t0*VV;

    // ---- prefetch chunk 0 ----
    float rx[25], rw0, rw1;
    {
        const float* gx = xbase + kkL*TV + tL*VV;
        #pragma unroll
        for (int u = 0; u < 25; u++) rx[u] = gx[u];
        int kkw = tid & 15, cow = tid >> 4;
        rw0 = w3[(co0 + cow     )*CI + kkw];
        rw1 = w3[(co0 + cow + 16)*CI + kkw];
    }

    for (int kb = 0; kb < 16; kb++) {
        // store prefetched chunk
        {
            float* sxp = xs + kkL*448 + tL*28;
            #pragma unroll
            for (int u = 0; u < 25; u++) sxp[u] = rx[u];
            int kkw = tid & 15, cow = tid >> 4;
            ws[kkw*34 + cow     ] = rw0;
            ws[kkw*34 + cow + 16] = rw1;
        }
        __syncthreads();
        // prefetch next chunk (overlaps compute)
        if (kb < 15) {
            const float* gx = xbase + ((kb+1)*16 + kkL)*TV + tL*VV;
            #pragma unroll
            for (int u = 0; u < 25; u++) rx[u] = gx[u];
            int k0 = (kb+1)*16;
            int kkw = tid & 15, cow = tid >> 4;
            rw0 = w3[(co0 + cow     )*CI + k0 + kkw];
            rw1 = w3[(co0 + cow + 16)*CI + k0 + kkw];
        }
        // compute
        #pragma unroll 4
        for (int kk = 0; kk < 16; kk++) {
            float2 a = *(const float2*)&ws[kk*34 + tx*2];
            const float4* brow = (const float4*)&xs[kk*448 + ty*28];
            #pragma unroll
            for (int q = 0; q < 7; q++) {
                float4 b = brow[q];
                int u0 = q*4;
                acc0[u0] += a.x*b.x;  acc1[u0] += a.y*b.x;
                if (u0+1 < 25) { acc0[u0+1] += a.x*b.y;  acc1[u0+1] += a.y*b.y; }
                if (u0+2 < 25) { acc0[u0+2] += a.x*b.z;  acc1[u0+2] += a.y*b.z; }
                if (u0+3 < 25) { acc0[u0+3] += a.x*b.w;  acc1[u0+3] += a.y*b.w; }
            }
        }
        __syncthreads();
    }

    // ---- x3 (+b3) to smem (per-thread private region; xs region is free now) ----
    float b3v0 = b3[co0 + tx*2], b3v1 = b3[co0 + tx*2 + 1];
    {
        float* p0 = x3s + (tx*2    )*X3_CO_STRIDE + ty*27;
        float* p1 = x3s + (tx*2 + 1)*X3_CO_STRIDE + ty*27;
        #pragma unroll
        for (int u = 0; u < 25; u++) { p0[u] = acc0[u] + b3v0; p1[u] = acc1[u] + b3v1; }
    }

    // ---- epilogue: out[co,t,v] = sum_u attn[co,u,v] * x3[co,t,u] ----
    size_t obase = (((size_t)n*CO + co0 + tx*2)*TT + t0 + ty)*VV;
    #pragma unroll
    for (int j = 0; j < 2; j++) {
        const float* arow = attn_s + (tx*2 + j)*ATTN_STRIDE;
        const float* x3r  = x3s + (tx*2 + j)*X3_CO_STRIDE + ty*27;
        float4 o0={0,0,0,0},o1={0,0,0,0},o2={0,0,0,0},o3={0,0,0,0},o4={0,0,0,0},o5={0,0,0,0};
        float o24 = 0.f;
        for (int u = 0; u < 25; u++) {
            float xv = x3r[u];
            const float4* av = (const float4*)(arow + u*28);
            float4 a0=av[0],a1=av[1],a2=av[2],a3=av[3],a4=av[4],a5=av[5];
            float  a24 = arow[u*28 + 24];
            o0.x += xv*a0.x; o0.y += xv*a0.y; o0.z += xv*a0.z; o0.w += xv*a0.w;
            o1.x += xv*a1.x; o1.y += xv*a1.y; o1.z += xv*a1.z; o1.w += xv*a1.w;
            o2.x += xv*a2.x; o2.y += xv*a2.y; o2.z += xv*a2.z; o2.w += xv*a2.w;
            o3.x += xv*a3.x; o3.y += xv*a3.y; o3.z += xv*a3.z; o3.w += xv*a3.w;
            o4.x += xv*a4.x; o4.y += xv*a4.y; o4.z += xv*a4.z; o4.w += xv*a4.w;
            o5.x += xv*a5.x; o5.y += xv*a5.y; o5.z += xv*a5.z; o5.w += xv*a5.w;
            o24  += xv*a24;
        }
        float* op = out + obase + (size_t)j*TT*VV;
        op[0]=o0.x;  op[1]=o0.y;  op[2]=o0.z;  op[3]=o0.w;
        op[4]=o1.x;  op[5]=o1.y;  op[6]=o1.z;  op[7]=o1.w;
        op[8]=o2.x;  op[9]=o2.y;  op[10]=o2.z; op[11]=o2.w;
        op[12]=o3.x; op[13]=o3.y; op[14]=o3.z; op[15]=o3.w;
        op[16]=o4.x; op[17]=o4.y; op[18]=o4.z; op[19]=o4.w;
        op[20]=o5.x; op[21]=o5.y; op[22]=o5.z; op[23]=o5.w;
        op[24]=o24;
    }
}

// ---------------- launch ----------------
extern "C" void kernel_launch(void* const* d_in, const int* in_sizes, int n_in,
                              void* d_out, int out_size) {
    const float* x  = (const float*)d_in[0];
    const float* A  = (const float*)d_in[1];
    const float* w1 = (const float*)d_in[2];
    const float* b1 = (const float*)d_in[3];
    const float* w2 = (const float*)d_in[4];
    const float* b2 = (const float*)d_in[5];
    const float* w3 = (const float*)d_in[6];
    const float* b3 = (const float*)d_in[7];
    const float* w4 = (const float*)d_in[8];
    const float* b4 = (const float*)d_in[9];
    // d_in[10] = threhold (unused by reference), d_in[11] = alpha == 1 (folded)
    float* out = (float*)d_out;

    cudaFuncSetAttribute(k_main, cudaFuncAttributeMaxDynamicSharedMemorySize,
                         SMEM_FLOATS * (int)sizeof(float));

    k_xm  <<<dim3(64, 64), 256>>>(x);
    k_x12 <<<64, 256>>>(w1, b1, w2, b2);
    k_aff <<<64, 256>>>();
    k_attn<<<dim3(10, 4, 64), 256>>>(w4, b4, A);
    k_main<<<dim3(32, 64), 256, SMEM_FLOATS * sizeof(float)>>>(x, w3, b3, out);
}

// round 3
// speedup vs baseline: 2.2208x; 2.2208x over previous
#include <cuda_runtime.h>
#include <cuda_bf16.h>
#include <cstdint>

#define NN 64
#define CI 256
#define CO 256
#define CR 32
#define TT 64
#define VV 25
#define TV 1600   // T*V
#define UV 625    // V*V
#define NROWS (NN*TV)       // 102400 flattened (n,t,v) rows
#define NTILES (NROWS/128)  // 800

// ---------------- scratch (device globals; no runtime allocation) ----------------
__device__ float g_xm[NN*CI*VV];
__device__ float g_x1[NN*CR*VV];
__device__ float g_x2[NN*CR*VV];
__device__ float g_aff[NN*CR*UV];
__device__ float g_attn[NN*CO*UV];                  // (n, co, u*25+v)
__device__ __nv_bfloat16 g_ahi[(size_t)NROWS*CI];   // x transposed hi split [row, c]
__device__ __nv_bfloat16 g_alo[(size_t)NROWS*CI];
__device__ __nv_bfloat16 g_bhi[CO*CI];              // w3 hi split [co, c]
__device__ __nv_bfloat16 g_blo[CO*CI];
__device__ float g_x3[(size_t)NROWS*CO];            // x3 [row=(n,t,u), co]

// ---------------- helpers ----------------
__device__ __forceinline__ uint32_t smem_u32(const void* p) {
    uint32_t a;
    asm("{ .reg .u64 t; cvta.to.shared.u64 t, %1; cvt.u32.u64 %0, t; }" : "=r"(a) : "l"(p));
    return a;
}
__device__ __forceinline__ uint32_t swz(uint32_t o) { return o ^ ((o >> 3) & 0x70); }

#define CPA(dst, src) asm volatile("cp.async.cg.shared.global [%0], [%1], 16;" \
                                   :: "r"(dst), "l"(src) : "memory")
#define CPC() asm volatile("cp.async.commit_group;" ::: "memory")
#define CPW(n) asm volatile("cp.async.wait_group %0;" :: "n"(n) : "memory")

__device__ __forceinline__ void ldsm4(uint32_t& r0, uint32_t& r1, uint32_t& r2, uint32_t& r3,
                                      uint32_t a) {
    asm volatile("ldmatrix.sync.aligned.m8n8.x4.shared.b16 {%0,%1,%2,%3}, [%4];"
                 : "=r"(r0), "=r"(r1), "=r"(r2), "=r"(r3) : "r"(a));
}
__device__ __forceinline__ void mma16816(float* d, const uint32_t* a, const uint32_t* b) {
    asm volatile("mma.sync.aligned.m16n8k16.row.col.f32.bf16.bf16.f32 "
                 "{%0,%1,%2,%3}, {%4,%5,%6,%7}, {%8,%9}, {%0,%1,%2,%3};"
                 : "+f"(d[0]), "+f"(d[1]), "+f"(d[2]), "+f"(d[3])
                 : "r"(a[0]), "r"(a[1]), "r"(a[2]), "r"(a[3]), "r"(b[0]), "r"(b[1]));
}

// ---------------- K0: xm = mean_t x ----------------
__global__ void k_xm(const float* __restrict__ x) {
    __shared__ float sx[4*TV];
    int n = blockIdx.y, cc = blockIdx.x;
    const float* xb = x + ((size_t)(n*CI + cc*4))*TV;
    for (int i = threadIdx.x; i < 4*TV; i += 256) sx[i] = xb[i];
    __syncthreads();
    if (threadIdx.x < 100) {
        int c = threadIdx.x / VV, v = threadIdx.x - c*VV;
        float s = 0.f;
        #pragma unroll
        for (int t = 0; t < TT; t++) s += sx[c*TV + t*VV + v];
        g_xm[n*(CI*VV) + cc*100 + threadIdx.x] = s * (1.0f/64.0f);
    }
}

// ---------------- K1: x1/x2 ----------------
__global__ void k_x12(const float* __restrict__ w1, const float* __restrict__ b1,
                      const float* __restrict__ w2, const float* __restrict__ b2) {
    __shared__ float xm_s[CI*VV];
    int n = blockIdx.x;
    for (int i = threadIdx.x; i < CI*VV; i += 256) xm_s[i] = g_xm[n*(CI*VV) + i];
    __syncthreads();
    for (int i = threadIdx.x; i < 2*CR*VV; i += 256) {
        int sel = i / (CR*VV);
        int rv  = i - sel*(CR*VV);
        int r = rv / VV, v = rv - r*VV;
        const float* w = sel ? w2 : w1;
        float s = sel ? b2[r] : b1[r];
        #pragma unroll 8
        for (int c = 0; c < CI; c++) s += w[r*CI + c] * xm_s[c*VV + v];
        (sel ? g_x2 : g_x1)[n*(CR*VV) + rv] = s;
    }
}

// ---------------- K2: aff = tanh(x1[u] - x2[v]) ----------------
__global__ void k_aff() {
    __shared__ float s1[CR*VV], s2[CR*VV];
    int n = blockIdx.x;
    for (int i = threadIdx.x; i < CR*VV; i += 256) {
        s1[i] = g_x1[n*(CR*VV) + i];
        s2[i] = g_x2[n*(CR*VV) + i];
    }
    __syncthreads();
    for (int i = threadIdx.x; i < CR*UV; i += 256) {
        int r = i / UV, uv = i - r*UV;
        int u = uv / VV, v = uv - u*VV;
        g_aff[n*(CR*UV) + i] = tanhf(s1[r*VV + u] - s2[r*VV + v]);
    }
}

// ---------------- K3: attn = w4@aff + b4 + A ----------------
__global__ void k_attn(const float* __restrict__ w4, const float* __restrict__ b4,
                       const float* __restrict__ A) {
    __shared__ __align__(16) float w4s[64*CR];
    __shared__ __align__(16) float affs[CR*64];
    int n = blockIdx.z, cot = blockIdx.y, uvt = blockIdx.x;
    int co0 = cot*64, uv0 = uvt*64;
    int tx = threadIdx.x & 15, ty = threadIdx.x >> 4;

    for (int i = threadIdx.x; i < 64*CR; i += 256) w4s[i] = w4[co0*CR + i];
    for (int i = threadIdx.x; i < CR*64; i += 256) {
        int r = i >> 6, c = i & 63;
        affs[i] = (uv0 + c < UV) ? g_aff[n*(CR*UV) + r*UV + uv0 + c] : 0.f;
    }
    __syncthreads();

    float acc[4][4] = {};
    #pragma unroll
    for (int k = 0; k < CR; k++) {
        float4 b = *(const float4*)&affs[k*64 + tx*4];
        #pragma unroll
        for (int i = 0; i < 4; i++) {
            float a = w4s[(ty*4 + i)*CR + k];
            acc[i][0] += a*b.x; acc[i][1] += a*b.y;
            acc[i][2] += a*b.z; acc[i][3] += a*b.w;
        }
    }
    #pragma unroll
    for (int i = 0; i < 4; i++) {
        int co = co0 + ty*4 + i;
        float bb = b4[co];
        #pragma unroll
        for (int j = 0; j < 4; j++) {
            int uv = uv0 + tx*4 + j;
            if (uv < UV)
                g_attn[((size_t)n*CO + co)*UV + uv] = acc[i][j] + bb + A[uv];
        }
    }
}

// ---------------- K4: w3 split to bf16 hi/lo ----------------
__global__ void k_w3cvt(const float* __restrict__ w3) {
    int i = blockIdx.x*1024 + threadIdx.x;
    float v = w3[i];
    __nv_bfloat16 hi = __float2bfloat16(v);
    g_bhi[i] = hi;
    g_blo[i] = __float2bfloat16(v - __bfloat162float(hi));
}

// ---------------- K5: transpose + split x -> g_ahi/g_alo [row=(n,tv), c] ----------------
__global__ __launch_bounds__(256) void k_xcvt(const float* __restrict__ x) {
    __shared__ float tile[32][33];
    int n = blockIdx.z, c0 = blockIdx.y*32, tv0 = blockIdx.x*32;
    int tx = threadIdx.x & 31, ty = threadIdx.x >> 5;   // 32 x 8
    #pragma unroll
    for (int i = 0; i < 4; i++) {
        int c = c0 + ty + i*8;
        tile[ty + i*8][tx] = x[((size_t)(n*CI + c))*TV + tv0 + tx];
    }
    __syncthreads();
    int wtx = threadIdx.x & 15, wty = threadIdx.x >> 4;  // 16 c-pairs x 16 tv
    #pragma unroll
    for (int p = 0; p < 2; p++) {
        int tvl = wty + p*16;
        float v0 = tile[wtx*2][tvl];
        float v1 = tile[wtx*2 + 1][tvl];
        __nv_bfloat16 h0 = __float2bfloat16(v0);
        __nv_bfloat16 h1 = __float2bfloat16(v1);
        __nv_bfloat162 hh; hh.x = h0; hh.y = h1;
        __nv_bfloat162 ll;
        ll.x = __float2bfloat16(v0 - __bfloat162float(h0));
        ll.y = __float2bfloat16(v1 - __bfloat162float(h1));
        size_t row = (size_t)n*TV + tv0 + tvl;
        *(__nv_bfloat162*)&g_ahi[row*CI + c0 + wtx*2] = hh;
        *(__nv_bfloat162*)&g_alo[row*CI + c0 + wtx*2] = ll;
    }
}

// ---------------- K6: HMMA GEMM  x3 = x @ w3^T + b3  (bf16 3-split, fp32 acc) ----------------
// CTA: 128 rows x 128 co, K=256 in 4 chunks of 64, cp.async double buffered.
// 8 warps: warp (wm = wid&3, wn = wid>>2) computes 32 rows x 64 co.
#define STAGE_BYTES 65536          // Ahi 16K | Alo 16K | Bhi 16K | Blo 16K
#define MMA_SMEM (2*STAGE_BYTES)

__global__ __launch_bounds__(256, 1) void k_mma(const float* __restrict__ b3) {
    extern __shared__ __align__(1024) char smem[];
    uint32_t sb = smem_u32(smem);
    int tid = threadIdx.x, lane = tid & 31, wid = tid >> 5;
    int tile = blockIdx.x, co0 = blockIdx.y * 128;

    const __nv_bfloat16* abh = g_ahi + (size_t)tile*128*CI;
    const __nv_bfloat16* abl = g_alo + (size_t)tile*128*CI;
    const __nv_bfloat16* bbh = g_bhi + (size_t)co0*CI;
    const __nv_bfloat16* bbl = g_blo + (size_t)co0*CI;

    // -------- async chunk loader: 128 rows x 64 k (x4 matrices) --------
    auto load_chunk = [&](int kb, int stage) {
        uint32_t s0 = sb + stage*STAGE_BYTES;
        const uint4* gah = (const uint4*)(abh + kb*64);
        const uint4* gal = (const uint4*)(abl + kb*64);
        const uint4* gbh = (const uint4*)(bbh + kb*64);
        const uint4* gbl = (const uint4*)(bbl + kb*64);
        int q = tid & 7;
        #pragma unroll
        for (int it = 0; it < 4; it++) {
            int r = (tid >> 3) + it*32;
            uint32_t so = swz((uint32_t)(r*128 + q*16));
            int gi = r*32 + q;               // row stride 256 bf16 = 32 uint4
            CPA(s0 +         so, gah + gi);
            CPA(s0 + 16384 + so, gal + gi);
            CPA(s0 + 32768 + so, gbh + gi);
            CPA(s0 + 49152 + so, gbl + gi);
        }
        CPC();
    };

    int m0 = (wid & 3) * 32, n0 = (wid >> 2) * 64;
    float acc[2][8][4];
    #pragma unroll
    for (int mt = 0; mt < 2; mt++)
        #pragma unroll
        for (int nt = 0; nt < 8; nt++)
            #pragma unroll
            for (int k = 0; k < 4; k++) acc[mt][nt][k] = 0.f;

    load_chunk(0, 0);
    load_chunk(1, 1);

    // per-lane ldmatrix address components
    int a_row = lane & 15;            // row within 16-row tile
    int a_seg = lane >> 4;            // 0/1 -> +16 bytes (k 8..15)
    int b_row = ((lane >> 4) & 1) * 8 + (lane & 7);
    int b_seg = (lane >> 3) & 1;

    #pragma unroll
    for (int kb = 0; kb < 4; kb++) {
        if (kb < 3) { CPW(1); } else { CPW(0); }
        __syncthreads();
        uint32_t s0 = sb + (kb & 1)*STAGE_BYTES;
        #pragma unroll
        for (int ks = 0; ks < 4; ks++) {
            uint32_t ah[2][4], al[2][4], bh[16], bl[16];
            #pragma unroll
            for (int mt = 0; mt < 2; mt++) {
                uint32_t off = swz((uint32_t)((m0 + mt*16 + a_row)*128 + ks*32 + a_seg*16));
                ldsm4(ah[mt][0], ah[mt][1], ah[mt][2], ah[mt][3], s0 + off);
                ldsm4(al[mt][0], al[mt][1], al[mt][2], al[mt][3], s0 + 16384 + off);
            }
            #pragma unroll
            for (int np = 0; np < 4; np++) {
                uint32_t off = swz((uint32_t)((n0 + np*16 + b_row)*128 + ks*32 + b_seg*16));
                ldsm4(bh[np*4+0], bh[np*4+1], bh[np*4+2], bh[np*4+3], s0 + 32768 + off);
                ldsm4(bl[np*4+0], bl[np*4+1], bl[np*4+2], bl[np*4+3], s0 + 49152 + off);
            }
            #pragma unroll
            for (int mt = 0; mt < 2; mt++)
                #pragma unroll
                for (int nt = 0; nt < 8; nt++) {
                    mma16816(acc[mt][nt], ah[mt], &bh[nt*2]);  // hi*hi
                    mma16816(acc[mt][nt], ah[mt], &bl[nt*2]);  // hi*lo
                    mma16816(acc[mt][nt], al[mt], &bh[nt*2]);  // lo*hi
                }
        }
        __syncthreads();
        if (kb < 2) load_chunk(kb + 2, kb & 1);
    }

    // -------- store x3 (+b3) --------
    size_t rowg0 = (size_t)tile * 128;
    #pragma unroll
    for (int mt = 0; mt < 2; mt++) {
        int r0 = m0 + mt*16 + (lane >> 2);
        #pragma unroll
        for (int nt = 0; nt < 8; nt++) {
            int c = co0 + n0 + nt*8 + (lane & 3)*2;
            float2 bb = *(const float2*)(b3 + c);
            float2 v0, v1;
            v0.x = acc[mt][nt][0] + bb.x;  v0.y = acc[mt][nt][1] + bb.y;
            v1.x = acc[mt][nt][2] + bb.x;  v1.y = acc[mt][nt][3] + bb.y;
            *(float2*)(g_x3 + (rowg0 + r0    )*CO + c) = v0;
            *(float2*)(g_x3 + (rowg0 + r0 + 8)*CO + c) = v1;
        }
    }
}

// ---------------- K7: out[n,co,t,v] = sum_u attn[n,co,u,v] * x3[n,(t,u),co] ----------------
__global__ __launch_bounds__(256) void k_out(float* __restrict__ out) {
    __shared__ __align__(16) float attn_s[8*700];   // 8 co x 25 u x 28(pad v)
    __shared__ __align__(16) float x3_s[32*25*8];   // [t][u][co]
    int n = blockIdx.y;
    int cot = blockIdx.x >> 1, tt = blockIdx.x & 1;
    int co0 = cot*8, t0 = tt*32;
    int tid = threadIdx.x;

    {
        const float* ab = g_attn + ((size_t)n*CO + co0)*UV;
        for (int i = tid; i < 8*700; i += 256) {
            int co = i / 700, rem = i - co*700;
            int u = rem / 28, v = rem - u*28;
            attn_s[i] = (v < VV) ? ab[co*UV + u*VV + v] : 0.f;
        }
        const float* xb = g_x3 + ((size_t)n*TV + t0*VV)*CO + co0;
        for (int i = tid; i < 32*25*8; i += 256) {
            int r = i >> 3, co = i & 7;      // r = t*25+u
            x3_s[i] = xb[(size_t)r*CO + co];
        }
    }
    __syncthreads();

    int co = tid & 7, tl = tid >> 3;
    const float* arow = attn_s + co*700;
    const float* x3r  = x3_s + tl*200 + co;
    float4 o0={0,0,0,0},o1={0,0,0,0},o2={0,0,0,0},o3={0,0,0,0},o4={0,0,0,0},o5={0,0,0,0};
    float o24 = 0.f;
    for (int u = 0; u < 25; u++) {
        float xv = x3r[u*8];
        const float4* av = (const float4*)(arow + u*28);
        float4 a0=av[0],a1=av[1],a2=av[2],a3=av[3],a4=av[4],a5=av[5];
        float  a24 = arow[u*28 + 24];
        o0.x += xv*a0.x; o0.y += xv*a0.y; o0.z += xv*a0.z; o0.w += xv*a0.w;
        o1.x += xv*a1.x; o1.y += xv*a1.y; o1.z += xv*a1.z; o1.w += xv*a1.w;
        o2.x += xv*a2.x; o2.y += xv*a2.y; o2.z += xv*a2.z; o2.w += xv*a2.w;
        o3.x += xv*a3.x; o3.y += xv*a3.y; o3.z += xv*a3.z; o3.w += xv*a3.w;
        o4.x += xv*a4.x; o4.y += xv*a4.y; o4.z += xv*a4.z; o4.w += xv*a4.w;
        o5.x += xv*a5.x; o5.y += xv*a5.y; o5.z += xv*a5.z; o5.w += xv*a5.w;
        o24  += xv*a24;
    }
    float* op = out + (((size_t)(n*CO + co0 + co))*TT + t0 + tl)*VV;
    op[0]=o0.x;  op[1]=o0.y;  op[2]=o0.z;  op[3]=o0.w;
    op[4]=o1.x;  op[5]=o1.y;  op[6]=o1.z;  op[7]=o1.w;
    op[8]=o2.x;  op[9]=o2.y;  op[10]=o2.z; op[11]=o2.w;
    op[12]=o3.x; op[13]=o3.y; op[14]=o3.z; op[15]=o3.w;
    op[16]=o4.x; op[17]=o4.y; op[18]=o4.z; op[19]=o4.w;
    op[20]=o5.x; op[21]=o5.y; op[22]=o5.z; op[23]=o5.w;
    op[24]=o24;
}

// ---------------- launch ----------------
extern "C" void kernel_launch(void* const* d_in, const int* in_sizes, int n_in,
                              void* d_out, int out_size) {
    const float* x  = (const float*)d_in[0];
    const float* A  = (const float*)d_in[1];
    const float* w1 = (const float*)d_in[2];
    const float* b1 = (const float*)d_in[3];
    const float* w2 = (const float*)d_in[4];
    const float* b2 = (const float*)d_in[5];
    const float* w3 = (const float*)d_in[6];
    const float* b3 = (const float*)d_in[7];
    const float* w4 = (const float*)d_in[8];
    const float* b4 = (const float*)d_in[9];
    float* out = (float*)d_out;

    cudaFuncSetAttribute(k_mma, cudaFuncAttributeMaxDynamicSharedMemorySize, MMA_SMEM);

    k_xm   <<<dim3(64, 64), 256>>>(x);
    k_x12  <<<64, 256>>>(w1, b1, w2, b2);
    k_aff  <<<64, 256>>>();
    k_attn <<<dim3(10, 4, 64), 256>>>(w4, b4, A);
    k_w3cvt<<<64, 1024>>>(w3);
    k_xcvt <<<dim3(50, 8, 64), 256>>>(x);
    k_mma  <<<dim3(NTILES, 2), 256, MMA_SMEM>>>(b3);
    k_out  <<<dim3(64, 64), 256>>>(out);
}